// round 16
// baseline (speedup 1.0000x reference)
#include <cuda_runtime.h>
#include <cuda_fp16.h>
#include <math.h>

#define NNODES 100000
#define KNB 16

// Scratch (bss, no allocation). h reused by both layers (sequential stream).
__device__ __align__(16) __half g_h[NNODES * 64];
__device__ __align__(16) float  g_x1[NNODES * 64];
__device__ float g_sd[NNODES];
__device__ float g_ss[NNODES];

// ---- helpers ---------------------------------------------------------------
__device__ __forceinline__ unsigned cvt_tf32(float f) {
    unsigned u;
    asm("cvt.rna.tf32.f32 %0, %1;" : "=r"(u) : "f"(f));
    return u;
}
__device__ __forceinline__ void mma_tf32(float* c,
    unsigned a0, unsigned a1, unsigned a2, unsigned a3,
    unsigned b0, unsigned b1)
{
    asm volatile(
        "mma.sync.aligned.m16n8k8.row.col.f32.tf32.tf32.f32 "
        "{%0,%1,%2,%3}, {%4,%5,%6,%7}, {%8,%9}, {%0,%1,%2,%3};"
        : "+f"(c[0]), "+f"(c[1]), "+f"(c[2]), "+f"(c[3])
        : "r"(a0), "r"(a1), "r"(a2), "r"(a3), "r"(b0), "r"(b1));
}
__device__ __forceinline__ unsigned smem_u32(const void* p) {
    unsigned a;
    asm("{ .reg .u64 t; cvta.to.shared.u64 t, %1; cvt.u32.u64 %0, t; }"
        : "=r"(a) : "l"(p));
    return a;
}
__device__ __forceinline__ void cp_async16(unsigned dst, const void* src, int sz) {
    asm volatile("cp.async.cg.shared.global [%0], [%1], 16, %2;"
                 :: "r"(dst), "l"(src), "r"(sz));
}

// ---------------------------------------------------------------------------
// GEMM h = x @ W (KD inner, 64 cols) on tf32 tensor cores + fused attention
// dots sd[i]=h[i].a[0:64], ss[i]=h[i].a[64:128]; h stored fp16.
// x tile cp.async'd (.cg) as RAW fp32 bits (tensor core truncates to tf32);
// the -3.52e-4 truncation bias is cancelled by scaling W (rna) at fill time.
// NEW: W stored as (k, k+4) PAIRS -> each mma's 2 B operands are ONE LDS.64.
//   Wp u64-layout: Wp[(o*4+q)*68 + n] = { W[8o+q][n], W[8o+q+4][n] }.
//   Stride 68 (= 4 mod 16) -> 16-lane phase banks 4q+g all distinct: no
//   conflicts. Mainloop LDS per k-step per warp: 20 -> 12.
// ---------------------------------------------------------------------------
template <int KD>
__global__ void __launch_bounds__(256) gemm_mma_kernel(
    const float* __restrict__ x, const float* __restrict__ W,
    const float* __restrict__ a, __half* __restrict__ h,
    float* __restrict__ sd, float* __restrict__ ss)
{
    constexpr int XS  = KD + 4;    // padded x row stride (u32 units)
    constexpr int WPS = 68;        // W pair-row stride (u64 units)
    constexpr int K4  = KD / 4;    // 16B chunks per x row
    constexpr int K4H = K4 / 2;    // chunks per stage
    extern __shared__ unsigned smem_u[];
    unsigned* Wsu = smem_u;                  // (KD/2) pair-rows x 68 u64
    unsigned* xsu = smem_u + KD * WPS;       // 128 x XS (raw fp32 bits)

    const int tid  = threadIdx.x;
    const int warp = tid >> 5;
    const int lane = tid & 31;
    const int q = lane & 3;
    const int g = lane >> 2;
    const int rowbase = blockIdx.x * 128;

    const float4* xg = reinterpret_cast<const float4*>(x + (size_t)rowbase * KD);
    const unsigned xsa = smem_u32(xsu);
    const int nvr = NNODES - rowbase;

    // Stage 0: k-chunks [0, K4H)
    #pragma unroll 4
    for (int i = tid; i < 128 * K4H; i += 256) {
        const int r = i / K4H, c = i % K4H;
        const unsigned dst = xsa + (unsigned)(r * XS + c * 4) * 4u;
        const int sz = (r < nvr) ? 16 : 0;
        cp_async16(dst, xg + (sz ? (r * K4 + c) : 0), sz);
    }
    asm volatile("cp.async.commit_group;");
    // Stage 1: k-chunks [K4H, K4)
    #pragma unroll 4
    for (int i = tid; i < 128 * K4H; i += 256) {
        const int r = i / K4H, c = K4H + i % K4H;
        const unsigned dst = xsa + (unsigned)(r * XS + c * 4) * 4u;
        const int sz = (r < nvr) ? 16 : 0;
        cp_async16(dst, xg + (sz ? (r * K4 + c) : 0), sz);
    }
    asm volatile("cp.async.commit_group;");

    // W tile: rna cvt + bias comp, scattered into (k,k+4) pair layout.
    {
        const float comp = 1.000352f;
        const float4* Wg = reinterpret_cast<const float4*>(W);
        #pragma unroll
        for (int i = tid; i < KD * 16; i += 256) {
            const float4 v = Wg[i];
            const int k = i >> 4, n4 = (i & 15) * 4;
            const int pr = (k >> 3) * 4 + (k & 3);   // pair row
            const int slot = (k >> 2) & 1;           // 0: k0+q, 1: k0+q+4
            unsigned* dst = &Wsu[2 * (pr * WPS + n4) + slot];
            dst[0] = cvt_tf32(v.x * comp);
            dst[2] = cvt_tf32(v.y * comp);
            dst[4] = cvt_tf32(v.z * comp);
            dst[6] = cvt_tf32(v.w * comp);
        }
    }

    float acc[8][4];
    #pragma unroll
    for (int nt = 0; nt < 8; nt++)
        #pragma unroll
        for (int j = 0; j < 4; j++) acc[nt][j] = 0.0f;

    const unsigned* xw = &xsu[(warp * 16) * XS];
    const uint2* Wp = reinterpret_cast<const uint2*>(Wsu);

    asm volatile("cp.async.wait_group 1;");
    __syncthreads();
    #pragma unroll
    for (int k0 = 0; k0 < KD / 2; k0 += 8) {
        const unsigned a0 = xw[g * XS + k0 + q];
        const unsigned a1 = xw[(g + 8) * XS + k0 + q];
        const unsigned a2 = xw[g * XS + k0 + q + 4];
        const unsigned a3 = xw[(g + 8) * XS + k0 + q + 4];
        const uint2* wrow = &Wp[((k0 >> 3) * 4 + q) * WPS + g];
        #pragma unroll
        for (int nt = 0; nt < 8; nt++) {
            const uint2 bb = wrow[nt * 8];    // LDS.64: (b0, b1)
            mma_tf32(acc[nt], a0, a1, a2, a3, bb.x, bb.y);
        }
    }
    asm volatile("cp.async.wait_group 0;");
    __syncthreads();
    #pragma unroll
    for (int k0 = KD / 2; k0 < KD; k0 += 8) {
        const unsigned a0 = xw[g * XS + k0 + q];
        const unsigned a1 = xw[(g + 8) * XS + k0 + q];
        const unsigned a2 = xw[g * XS + k0 + q + 4];
        const unsigned a3 = xw[(g + 8) * XS + k0 + q + 4];
        const uint2* wrow = &Wp[((k0 >> 3) * 4 + q) * WPS + g];
        #pragma unroll
        for (int nt = 0; nt < 8; nt++) {
            const uint2 bb = wrow[nt * 8];
            mma_tf32(acc[nt], a0, a1, a2, a3, bb.x, bb.y);
        }
    }

    // Fused attention dots. Thread owns rows (16w+g, 16w+g+8), cols {8nt+2q,+1}.
    float pd0 = 0.f, ps0 = 0.f, pd1 = 0.f, ps1 = 0.f;
    #pragma unroll
    for (int nt = 0; nt < 8; nt++) {
        const float2 av = reinterpret_cast<const float2*>(a)[nt * 4 + q];
        const float2 bv = reinterpret_cast<const float2*>(a + 64)[nt * 4 + q];
        pd0 += acc[nt][0] * av.x + acc[nt][1] * av.y;
        ps0 += acc[nt][0] * bv.x + acc[nt][1] * bv.y;
        pd1 += acc[nt][2] * av.x + acc[nt][3] * av.y;
        ps1 += acc[nt][2] * bv.x + acc[nt][3] * bv.y;
    }
    #pragma unroll
    for (int off = 2; off >= 1; off >>= 1) {
        pd0 += __shfl_xor_sync(0xffffffffu, pd0, off);
        ps0 += __shfl_xor_sync(0xffffffffu, ps0, off);
        pd1 += __shfl_xor_sync(0xffffffffu, pd1, off);
        ps1 += __shfl_xor_sync(0xffffffffu, ps1, off);
    }

    const int row0 = rowbase + warp * 16 + g;
    const int row1 = row0 + 8;
    if (q == 0) {
        if (row0 < NNODES) { sd[row0] = pd0; ss[row0] = ps0; }
        if (row1 < NNODES) { sd[row1] = pd1; ss[row1] = ps1; }
    }
    if (row0 < NNODES) {
        #pragma unroll
        for (int nt = 0; nt < 8; nt++) {
            const __half2 hv = __floats2half2_rn(acc[nt][0], acc[nt][1]);
            *reinterpret_cast<__half2*>(&h[(size_t)row0 * 64 + nt * 8 + 2 * q]) = hv;
        }
    }
    if (row1 < NNODES) {
        #pragma unroll
        for (int nt = 0; nt < 8; nt++) {
            const __half2 hv = __floats2half2_rn(acc[nt][2], acc[nt][3]);
            *reinterpret_cast<__half2*>(&h[(size_t)row1 * 64 + nt * 8 + 2 * q]) = hv;
        }
    }
}

// ---------------------------------------------------------------------------
// Attention softmax (K=16) + fp16 gather + bias + relu.  TWO nodes per warp;
// lane owns 4 feature cols (uint2 = 2 half2). HFMA2 accumulation with the
// att weight pre-packed as replicated half2 and shuffled as bits.
// (R11 formulation: best measured; regs 32, occ ~87%.)
// ---------------------------------------------------------------------------
__global__ void __launch_bounds__(256) agg_kernel(
    const uint2* __restrict__ hh, const int* __restrict__ ecol,
    const float* __restrict__ sd, const float* __restrict__ ss,
    const float* __restrict__ b, float4* __restrict__ out)
{
    const int warp = (blockIdx.x * blockDim.x + threadIdx.x) >> 5;
    const int lane = threadIdx.x & 31;
    const int l16  = lane & 15;
    const int node = warp * 2 + (lane >> 4);

    const int col = ecol[warp * 32 + lane];   // coalesced

    float ev = sd[node] + ss[col];
    ev = (ev > 0.0f) ? ev : 0.2f * ev;        // leaky_relu slope 0.2

    float m = ev;
    #pragma unroll
    for (int off = 8; off >= 1; off >>= 1)
        m = fmaxf(m, __shfl_xor_sync(0xffffffffu, m, off));
    const float ex = __expf(ev - m);
    float s = ex;
    #pragma unroll
    for (int off = 8; off >= 1; off >>= 1)
        s += __shfl_xor_sync(0xffffffffu, s, off);
    const float att = ex / s;

    const __half2 hatt = __float2half2_rn(att);
    const unsigned hatt_u = *reinterpret_cast<const unsigned*>(&hatt);

    __half2 accA = __float2half2_rn(0.0f);
    __half2 accB = accA;
    #pragma unroll
    for (int k = 0; k < KNB; k++) {
        const int      ck = __shfl_sync(0xffffffffu, col, k, 16);
        const unsigned au = __shfl_sync(0xffffffffu, hatt_u, k, 16);
        const uint2    hv = hh[(size_t)ck * 16 + l16];
        const __half2  pa = *reinterpret_cast<const __half2*>(&au);
        accA = __hfma2(pa, *reinterpret_cast<const __half2*>(&hv.x), accA);
        accB = __hfma2(pa, *reinterpret_cast<const __half2*>(&hv.y), accB);
    }

    const float2 rA = __half22float2(accA);
    const float2 rB = __half22float2(accB);
    const float4 bv = reinterpret_cast<const float4*>(b)[l16];
    float4 o;
    o.x = fmaxf(rA.x + bv.x, 0.0f);
    o.y = fmaxf(rA.y + bv.y, 0.0f);
    o.z = fmaxf(rB.x + bv.z, 0.0f);
    o.w = fmaxf(rB.y + bv.w, 0.0f);
    out[(size_t)node * 16 + l16] = o;
}

// ---------------------------------------------------------------------------
extern "C" void kernel_launch(void* const* d_in, const int* in_sizes, int n_in,
                              void* d_out, int out_size)
{
    const float* x    = (const float*)d_in[0];
    // d_in[1] = edge_row: exactly K per node, row-sorted -> implicit, unused
    const int*   ecol = (const int*)d_in[2];
    const float* W1   = (const float*)d_in[3];
    const float* a1   = (const float*)d_in[4];
    const float* b1   = (const float*)d_in[5];
    const float* W2   = (const float*)d_in[6];
    const float* a2   = (const float*)d_in[7];
    const float* b2   = (const float*)d_in[8];

    __half* h;  float *x1, *sd, *ss;
    cudaGetSymbolAddress((void**)&h,  g_h);
    cudaGetSymbolAddress((void**)&x1, g_x1);
    cudaGetSymbolAddress((void**)&sd, g_sd);
    cudaGetSymbolAddress((void**)&ss, g_ss);

    const int smem1 = (128 * 68 + 128 * 132) * 4;   // ~100 KB
    const int smem2 = (64 * 68 + 128 * 68) * 4;     // ~51 KB
    cudaFuncSetAttribute(gemm_mma_kernel<128>,
                         cudaFuncAttributeMaxDynamicSharedMemorySize, smem1);
    cudaFuncSetAttribute(gemm_mma_kernel<64>,
                         cudaFuncAttributeMaxDynamicSharedMemorySize, smem2);

    const int gemm_blocks = (NNODES + 127) / 128;   // 782
    const int agg_blocks  = NNODES / 16;            // 6250 (8 warps x 2 nodes)

    // Layer 1
    gemm_mma_kernel<128><<<gemm_blocks, 256, smem1>>>(x, W1, a1, h, sd, ss);
    agg_kernel<<<agg_blocks, 256>>>((const uint2*)h, ecol, sd, ss, b1,
                                    (float4*)x1);
    // Layer 2
    gemm_mma_kernel<64><<<gemm_blocks, 256, smem2>>>(x1, W2, a2, h, sd, ss);
    agg_kernel<<<agg_blocks, 256>>>((const uint2*)h, ecol, sd, ss, b2,
                                    (float4*)d_out);
}

// round 17
// speedup vs baseline: 1.0571x; 1.0571x over previous
#include <cuda_runtime.h>
#include <cuda_fp16.h>
#include <math.h>

#define NNODES 100000
#define KNB 16

// Scratch (bss, no allocation). h reused by both layers (sequential stream).
__device__ __align__(16) __half g_h[NNODES * 64];
__device__ __align__(16) float  g_x1[NNODES * 64];
__device__ float g_sd[NNODES];
__device__ float g_ss[NNODES];

// ---- helpers ---------------------------------------------------------------
__device__ __forceinline__ unsigned cvt_tf32(float f) {
    unsigned u;
    asm("cvt.rna.tf32.f32 %0, %1;" : "=r"(u) : "f"(f));
    return u;
}
__device__ __forceinline__ void mma_tf32(float* c,
    unsigned a0, unsigned a1, unsigned a2, unsigned a3,
    unsigned b0, unsigned b1)
{
    asm volatile(
        "mma.sync.aligned.m16n8k8.row.col.f32.tf32.tf32.f32 "
        "{%0,%1,%2,%3}, {%4,%5,%6,%7}, {%8,%9}, {%0,%1,%2,%3};"
        : "+f"(c[0]), "+f"(c[1]), "+f"(c[2]), "+f"(c[3])
        : "r"(a0), "r"(a1), "r"(a2), "r"(a3), "r"(b0), "r"(b1));
}
__device__ __forceinline__ unsigned smem_u32(const void* p) {
    unsigned a;
    asm("{ .reg .u64 t; cvta.to.shared.u64 t, %1; cvt.u32.u64 %0, t; }"
        : "=r"(a) : "l"(p));
    return a;
}
__device__ __forceinline__ void cp_async16(unsigned dst, const void* src, int sz) {
    asm volatile("cp.async.cg.shared.global [%0], [%1], 16, %2;"
                 :: "r"(dst), "l"(src), "r"(sz));
}

// ---------------------------------------------------------------------------
// GEMM h = x @ W (KD inner, 64 cols) on tf32 tensor cores + fused attention
// dots sd[i]=h[i].a[0:64], ss[i]=h[i].a[64:128]; h stored fp16.
// x tile cp.async'd (.cg) as RAW fp32 bits (tensor core truncates to tf32);
// the -3.52e-4 truncation bias is cancelled by scaling W (rna) at fill time.
// W stored as (k, k+4) pairs -> each mma's 2 B operands are one LDS.64.
// NEW: h is restaged through smem (stride 72 halves -> STS banks 4g+q all
// distinct) and copied out with one contiguous 128B row per STG warp-instr:
// store wavefronts per block drop 2048 -> ~176.
// ---------------------------------------------------------------------------
template <int KD>
__global__ void __launch_bounds__(256) gemm_mma_kernel(
    const float* __restrict__ x, const float* __restrict__ W,
    const float* __restrict__ a, __half* __restrict__ h,
    float* __restrict__ sd, float* __restrict__ ss)
{
    constexpr int XS  = KD + 4;    // padded x row stride (u32 units)
    constexpr int WPS = 68;        // W pair-row stride (u64 units)
    constexpr int K4  = KD / 4;    // 16B chunks per x row
    constexpr int K4H = K4 / 2;    // chunks per stage
    extern __shared__ unsigned smem_u[];
    unsigned* Wsu = smem_u;                  // (KD/2) pair-rows x 68 u64
    unsigned* xsu = smem_u + KD * WPS;       // 128 x XS (raw fp32 bits)

    const int tid  = threadIdx.x;
    const int warp = tid >> 5;
    const int lane = tid & 31;
    const int q = lane & 3;
    const int g = lane >> 2;
    const int rowbase = blockIdx.x * 128;

    const float4* xg = reinterpret_cast<const float4*>(x + (size_t)rowbase * KD);
    const unsigned xsa = smem_u32(xsu);
    const int nvr = NNODES - rowbase;

    // Stage 0: k-chunks [0, K4H)
    #pragma unroll 4
    for (int i = tid; i < 128 * K4H; i += 256) {
        const int r = i / K4H, c = i % K4H;
        const unsigned dst = xsa + (unsigned)(r * XS + c * 4) * 4u;
        const int sz = (r < nvr) ? 16 : 0;
        cp_async16(dst, xg + (sz ? (r * K4 + c) : 0), sz);
    }
    asm volatile("cp.async.commit_group;");
    // Stage 1: k-chunks [K4H, K4)
    #pragma unroll 4
    for (int i = tid; i < 128 * K4H; i += 256) {
        const int r = i / K4H, c = K4H + i % K4H;
        const unsigned dst = xsa + (unsigned)(r * XS + c * 4) * 4u;
        const int sz = (r < nvr) ? 16 : 0;
        cp_async16(dst, xg + (sz ? (r * K4 + c) : 0), sz);
    }
    asm volatile("cp.async.commit_group;");

    // W tile: rna cvt + bias comp, scattered into (k,k+4) pair layout.
    {
        const float comp = 1.000352f;
        const float4* Wg = reinterpret_cast<const float4*>(W);
        #pragma unroll
        for (int i = tid; i < KD * 16; i += 256) {
            const float4 v = Wg[i];
            const int k = i >> 4, n4 = (i & 15) * 4;
            const int pr = (k >> 3) * 4 + (k & 3);   // pair row
            const int slot = (k >> 2) & 1;           // 0: k0+q, 1: k0+q+4
            unsigned* dst = &Wsu[2 * (pr * WPS + n4) + slot];
            dst[0] = cvt_tf32(v.x * comp);
            dst[2] = cvt_tf32(v.y * comp);
            dst[4] = cvt_tf32(v.z * comp);
            dst[6] = cvt_tf32(v.w * comp);
        }
    }

    float acc[8][4];
    #pragma unroll
    for (int nt = 0; nt < 8; nt++)
        #pragma unroll
        for (int j = 0; j < 4; j++) acc[nt][j] = 0.0f;

    const unsigned* xw = &xsu[(warp * 16) * XS];
    const uint2* Wp = reinterpret_cast<const uint2*>(Wsu);

    asm volatile("cp.async.wait_group 1;");
    __syncthreads();
    #pragma unroll
    for (int k0 = 0; k0 < KD / 2; k0 += 8) {
        const unsigned a0 = xw[g * XS + k0 + q];
        const unsigned a1 = xw[(g + 8) * XS + k0 + q];
        const unsigned a2 = xw[g * XS + k0 + q + 4];
        const unsigned a3 = xw[(g + 8) * XS + k0 + q + 4];
        const uint2* wrow = &Wp[((k0 >> 3) * 4 + q) * WPS + g];
        #pragma unroll
        for (int nt = 0; nt < 8; nt++) {
            const uint2 bb = wrow[nt * 8];    // LDS.64: (b0, b1)
            mma_tf32(acc[nt], a0, a1, a2, a3, bb.x, bb.y);
        }
    }
    asm volatile("cp.async.wait_group 0;");
    __syncthreads();
    #pragma unroll
    for (int k0 = KD / 2; k0 < KD; k0 += 8) {
        const unsigned a0 = xw[g * XS + k0 + q];
        const unsigned a1 = xw[(g + 8) * XS + k0 + q];
        const unsigned a2 = xw[g * XS + k0 + q + 4];
        const unsigned a3 = xw[(g + 8) * XS + k0 + q + 4];
        const uint2* wrow = &Wp[((k0 >> 3) * 4 + q) * WPS + g];
        #pragma unroll
        for (int nt = 0; nt < 8; nt++) {
            const uint2 bb = wrow[nt * 8];
            mma_tf32(acc[nt], a0, a1, a2, a3, bb.x, bb.y);
        }
    }

    // Fused attention dots. Thread owns rows (16w+g, 16w+g+8), cols {8nt+2q,+1}.
    float pd0 = 0.f, ps0 = 0.f, pd1 = 0.f, ps1 = 0.f;
    #pragma unroll
    for (int nt = 0; nt < 8; nt++) {
        const float2 av = reinterpret_cast<const float2*>(a)[nt * 4 + q];
        const float2 bv = reinterpret_cast<const float2*>(a + 64)[nt * 4 + q];
        pd0 += acc[nt][0] * av.x + acc[nt][1] * av.y;
        ps0 += acc[nt][0] * bv.x + acc[nt][1] * bv.y;
        pd1 += acc[nt][2] * av.x + acc[nt][3] * av.y;
        ps1 += acc[nt][2] * bv.x + acc[nt][3] * bv.y;
    }
    #pragma unroll
    for (int off = 2; off >= 1; off >>= 1) {
        pd0 += __shfl_xor_sync(0xffffffffu, pd0, off);
        ps0 += __shfl_xor_sync(0xffffffffu, ps0, off);
        pd1 += __shfl_xor_sync(0xffffffffu, pd1, off);
        ps1 += __shfl_xor_sync(0xffffffffu, ps1, off);
    }

    const int row0 = rowbase + warp * 16 + g;
    const int row1 = row0 + 8;
    if (q == 0) {
        if (row0 < NNODES) { sd[row0] = pd0; ss[row0] = ps0; }
        if (row1 < NNODES) { sd[row1] = pd1; ss[row1] = ps1; }
    }

    // ---- h restage: regs -> smem (conflict-free) -> coalesced STG ----------
    __syncthreads();          // mainloop reads of xsu done; reuse xsu as stage
    __half* hs = reinterpret_cast<__half*>(xsu);    // 128 rows x 72-half stride
    {
        const int r0 = warp * 16 + g;
        #pragma unroll
        for (int nt = 0; nt < 8; nt++) {
            // u32 bank = 4g + q (+4nt): all 32 lanes distinct -> conflict-free
            *reinterpret_cast<__half2*>(&hs[r0 * 72 + nt * 8 + 2 * q]) =
                __floats2half2_rn(acc[nt][0], acc[nt][1]);
            *reinterpret_cast<__half2*>(&hs[(r0 + 8) * 72 + nt * 8 + 2 * q]) =
                __floats2half2_rn(acc[nt][2], acc[nt][3]);
        }
    }
    __syncthreads();
    {
        const unsigned* hsu = reinterpret_cast<const unsigned*>(hs); // stride 36
        unsigned* hg = reinterpret_cast<unsigned*>(h);
        const int c = tid & 31;
        #pragma unroll
        for (int pass = 0; pass < 16; pass++) {
            const int r = pass * 8 + (tid >> 5);
            const unsigned v = hsu[r * 36 + c];
            const int row = rowbase + r;
            if (row < NNODES)
                hg[(size_t)row * 32 + c] = v;   // 128B contiguous per warp
        }
    }
}

// ---------------------------------------------------------------------------
// Attention softmax (K=16) + fp16 gather + bias + relu.  TWO nodes per warp;
// lane owns 4 feature cols (uint2 = 2 half2). HFMA2 accumulation with the
// att weight pre-packed as replicated half2 and shuffled as bits.
// ---------------------------------------------------------------------------
__global__ void __launch_bounds__(256) agg_kernel(
    const uint2* __restrict__ hh, const int* __restrict__ ecol,
    const float* __restrict__ sd, const float* __restrict__ ss,
    const float* __restrict__ b, float4* __restrict__ out)
{
    const int warp = (blockIdx.x * blockDim.x + threadIdx.x) >> 5;
    const int lane = threadIdx.x & 31;
    const int l16  = lane & 15;
    const int node = warp * 2 + (lane >> 4);

    const int col = ecol[warp * 32 + lane];   // coalesced

    float ev = sd[node] + ss[col];
    ev = (ev > 0.0f) ? ev : 0.2f * ev;        // leaky_relu slope 0.2

    float m = ev;
    #pragma unroll
    for (int off = 8; off >= 1; off >>= 1)
        m = fmaxf(m, __shfl_xor_sync(0xffffffffu, m, off));
    const float ex = __expf(ev - m);
    float s = ex;
    #pragma unroll
    for (int off = 8; off >= 1; off >>= 1)
        s += __shfl_xor_sync(0xffffffffu, s, off);
    const float att = ex / s;

    const __half2 hatt = __float2half2_rn(att);
    const unsigned hatt_u = *reinterpret_cast<const unsigned*>(&hatt);

    __half2 accA = __float2half2_rn(0.0f);
    __half2 accB = accA;
    #pragma unroll
    for (int k = 0; k < KNB; k++) {
        const int      ck = __shfl_sync(0xffffffffu, col, k, 16);
        const unsigned au = __shfl_sync(0xffffffffu, hatt_u, k, 16);
        const uint2    hv = hh[(size_t)ck * 16 + l16];
        const __half2  pa = *reinterpret_cast<const __half2*>(&au);
        accA = __hfma2(pa, *reinterpret_cast<const __half2*>(&hv.x), accA);
        accB = __hfma2(pa, *reinterpret_cast<const __half2*>(&hv.y), accB);
    }

    const float2 rA = __half22float2(accA);
    const float2 rB = __half22float2(accB);
    const float4 bv = reinterpret_cast<const float4*>(b)[l16];
    float4 o;
    o.x = fmaxf(rA.x + bv.x, 0.0f);
    o.y = fmaxf(rA.y + bv.y, 0.0f);
    o.z = fmaxf(rB.x + bv.z, 0.0f);
    o.w = fmaxf(rB.y + bv.w, 0.0f);
    out[(size_t)node * 16 + l16] = o;
}

// ---------------------------------------------------------------------------
extern "C" void kernel_launch(void* const* d_in, const int* in_sizes, int n_in,
                              void* d_out, int out_size)
{
    const float* x    = (const float*)d_in[0];
    // d_in[1] = edge_row: exactly K per node, row-sorted -> implicit, unused
    const int*   ecol = (const int*)d_in[2];
    const float* W1   = (const float*)d_in[3];
    const float* a1   = (const float*)d_in[4];
    const float* b1   = (const float*)d_in[5];
    const float* W2   = (const float*)d_in[6];
    const float* a2   = (const float*)d_in[7];
    const float* b2   = (const float*)d_in[8];

    __half* h;  float *x1, *sd, *ss;
    cudaGetSymbolAddress((void**)&h,  g_h);
    cudaGetSymbolAddress((void**)&x1, g_x1);
    cudaGetSymbolAddress((void**)&sd, g_sd);
    cudaGetSymbolAddress((void**)&ss, g_ss);

    // xsu region must also hold the 128x72-half h stage (18,432 B):
    //   KD=128: xsu = 128*132*4 = 67,584 B  (ok)
    //   KD=64 : xsu = 128*68*4  = 34,816 B  (ok)
    const int smem1 = (128 * 68 + 128 * 132) * 4;   // ~100 KB
    const int smem2 = (64 * 68 + 128 * 68) * 4;     // ~51 KB
    cudaFuncSetAttribute(gemm_mma_kernel<128>,
                         cudaFuncAttributeMaxDynamicSharedMemorySize, smem1);
    cudaFuncSetAttribute(gemm_mma_kernel<64>,
                         cudaFuncAttributeMaxDynamicSharedMemorySize, smem2);

    const int gemm_blocks = (NNODES + 127) / 128;   // 782
    const int agg_blocks  = NNODES / 16;            // 6250 (8 warps x 2 nodes)

    // Layer 1
    gemm_mma_kernel<128><<<gemm_blocks, 256, smem1>>>(x, W1, a1, h, sd, ss);
    agg_kernel<<<agg_blocks, 256>>>((const uint2*)h, ecol, sd, ss, b1,
                                    (float4*)x1);
    // Layer 2
    gemm_mma_kernel<64><<<gemm_blocks, 256, smem2>>>(x1, W2, a2, h, sd, ss);
    agg_kernel<<<agg_blocks, 256>>>((const uint2*)h, ecol, sd, ss, b2,
                                    (float4*)d_out);
}